// round 1
// baseline (speedup 1.0000x reference)
#include <cuda_runtime.h>
#include <math.h>

#define BB 16
#define SS 8192
#define DD 512
#define SCALE_F 0.125

// ---------------- scratch (__device__ globals; no allocations allowed) --------
__device__ double        g_hs[BB * DD];        // sum of normalized tokens per batch (fp64)
__device__ float         g_v[BB * DD];         // v[b] = Wq^T (Wk hs[b])
__device__ float         g_invnorm[BB * SS];   // 1/max(||hidden_row||, 1e-12)
__device__ unsigned char g_hard[BB * SS];      // boundary bits
__device__ int           g_keptidx[BB * SS];   // compacted kept indices per batch
__device__ int           g_count[BB];          // kept counts

// ---------------- kernel 0: zero hs ------------------------------------------
__global__ void zero_hs_kernel() {
    int i = blockIdx.x * blockDim.x + threadIdx.x;
    if (i < BB * DD) g_hs[i] = 0.0;
}

// ---------------- kernel 1: per-token norm + hs accumulation -----------------
// grid = 512 blocks (32 per batch), 256 threads (8 warps), warp = 32 tokens
__global__ void norm_hs_kernel(const float* __restrict__ hidden) {
    __shared__ double sh_acc[DD];
    int warp = threadIdx.x >> 5;
    int lane = threadIdx.x & 31;
    int batch = blockIdx.x >> 5;                    // 32 blocks per batch
    int tok0  = ((blockIdx.x & 31) * 8 + warp) * 32;

    for (int i = threadIdx.x; i < DD; i += blockDim.x) sh_acc[i] = 0.0;
    __syncthreads();

    double acc[16];
#pragma unroll
    for (int k = 0; k < 16; k++) acc[k] = 0.0;

    const float4* base = (const float4*)(hidden + (size_t)batch * SS * DD);
    for (int t = 0; t < 32; t++) {
        int tok = tok0 + t;
        const float4* row = base + (size_t)tok * (DD / 4);
        float4 x[4];
#pragma unroll
        for (int k = 0; k < 4; k++) x[k] = row[lane + 32 * k];
        double ss = 0.0;
#pragma unroll
        for (int k = 0; k < 4; k++) {
            ss += (double)x[k].x * (double)x[k].x + (double)x[k].y * (double)x[k].y
                + (double)x[k].z * (double)x[k].z + (double)x[k].w * (double)x[k].w;
        }
#pragma unroll
        for (int o = 16; o > 0; o >>= 1) ss += __shfl_down_sync(0xffffffffu, ss, o);
        ss = __shfl_sync(0xffffffffu, ss, 0);
        double inv = 1.0 / fmax(sqrt(ss), 1e-12);
        if (lane == 0) g_invnorm[batch * SS + tok] = (float)inv;
#pragma unroll
        for (int k = 0; k < 4; k++) {
            acc[4 * k + 0] += (double)x[k].x * inv;
            acc[4 * k + 1] += (double)x[k].y * inv;
            acc[4 * k + 2] += (double)x[k].z * inv;
            acc[4 * k + 3] += (double)x[k].w * inv;
        }
    }
    // combine the 8 warps in shared (8-way contention max), then 512 global atomics/block
#pragma unroll
    for (int k = 0; k < 4; k++) {
        int c = 4 * (lane + 32 * k);
        atomicAdd(&sh_acc[c + 0], acc[4 * k + 0]);
        atomicAdd(&sh_acc[c + 1], acc[4 * k + 1]);
        atomicAdd(&sh_acc[c + 2], acc[4 * k + 2]);
        atomicAdd(&sh_acc[c + 3], acc[4 * k + 3]);
    }
    __syncthreads();
    for (int i = threadIdx.x; i < DD; i += blockDim.x)
        atomicAdd(&g_hs[batch * DD + i], sh_acc[i]);
}

// ---------------- kernel 2: v[b] = Wq^T (Wk hs[b])  (fp64, tiny) -------------
// grid = 16 blocks (one per batch), 512 threads
__global__ void matvec_kernel(const float* __restrict__ Wq, const float* __restrict__ Wk) {
    __shared__ double sh_hs[DD];
    __shared__ double sh_t[DD];
    int b = blockIdx.x;
    int tid = threadIdx.x;
    sh_hs[tid] = g_hs[b * DD + tid];
    __syncthreads();

    int warp = tid >> 5, lane = tid & 31;  // 16 warps
    for (int d = warp; d < DD; d += 16) {
        const float* wrow = Wk + (size_t)d * DD;
        double s = 0.0;
        for (int e = lane; e < DD; e += 32) s += (double)wrow[e] * sh_hs[e];
#pragma unroll
        for (int o = 16; o > 0; o >>= 1) s += __shfl_down_sync(0xffffffffu, s, o);
        if (lane == 0) sh_t[d] = s;
    }
    __syncthreads();

    // v[e] = sum_d Wq[d,e] * t[d]  (coalesced across tid = e)
    double acc = 0.0;
    for (int d = 0; d < DD; d++) acc += (double)Wq[(size_t)d * DD + tid] * sh_t[d];
    g_v[b * DD + tid] = (float)acc;
}

// ---------------- kernel 3: scores + hard bits --------------------------------
// same token mapping as kernel 1
__global__ void scores_kernel(const float* __restrict__ hidden,
                              const float* __restrict__ noise) {
    __shared__ float sh_v[DD];
    int warp = threadIdx.x >> 5;
    int lane = threadIdx.x & 31;
    int batch = blockIdx.x >> 5;
    int tok0  = ((blockIdx.x & 31) * 8 + warp) * 32;

    for (int i = threadIdx.x; i < DD; i += blockDim.x) sh_v[i] = g_v[batch * DD + i];
    __syncthreads();

    const float4* base = (const float4*)(hidden + (size_t)batch * SS * DD);
    const float4* vv = (const float4*)sh_v;
    for (int t = 0; t < 32; t++) {
        int tok = tok0 + t;
        const float4* row = base + (size_t)tok * (DD / 4);
        double dot = 0.0;
#pragma unroll
        for (int k = 0; k < 4; k++) {
            float4 x = row[lane + 32 * k];
            float4 w = vv[lane + 32 * k];
            dot += (double)x.x * (double)w.x + (double)x.y * (double)w.y
                 + (double)x.z * (double)w.z + (double)x.w * (double)w.w;
        }
#pragma unroll
        for (int o = 16; o > 0; o >>= 1) dot += __shfl_down_sync(0xffffffffu, dot, o);
        if (lane == 0) {
            int g = batch * SS + tok;
            double score = SCALE_F * (double)g_invnorm[g] * dot;
            float nz = noise[g];
            double logistic = (double)logf(nz) - (double)log1pf(-nz);
            g_hard[g] = (score + logistic > 0.0) ? 1 : 0;
        }
    }
}

// ---------------- kernel 4: per-batch stable compaction scan ------------------
// grid = 16 blocks (one per batch), 1024 threads, 8 contiguous tokens/thread
__global__ void scan_kernel() {
    int b = blockIdx.x;
    int tid = threadIdx.x;
    const int TPT = SS / 1024;  // 8
    int base = b * SS + tid * TPT;

    int loc[TPT];
    int cnt = 0;
#pragma unroll
    for (int i = 0; i < TPT; i++) { loc[i] = g_hard[base + i]; cnt += loc[i]; }

    int lane = tid & 31, warp = tid >> 5;
    int v = cnt;
#pragma unroll
    for (int o = 1; o < 32; o <<= 1) {
        int n = __shfl_up_sync(0xffffffffu, v, o);
        if (lane >= o) v += n;
    }
    __shared__ int wsum[32];
    if (lane == 31) wsum[warp] = v;
    __syncthreads();
    if (warp == 0) {
        int w = wsum[lane];
#pragma unroll
        for (int o = 1; o < 32; o <<= 1) {
            int n = __shfl_up_sync(0xffffffffu, w, o);
            if (lane >= o) w += n;
        }
        wsum[lane] = w;
    }
    __syncthreads();
    int excl = (v - cnt) + (warp > 0 ? wsum[warp - 1] : 0);

    int pos = excl;
#pragma unroll
    for (int i = 0; i < TPT; i++)
        if (loc[i]) g_keptidx[b * SS + (pos++)] = tid * TPT + i;
    if (tid == 1023) g_count[b] = excl + cnt;
}

// ---------------- kernel 5: write pooled (gather kept rows, zero the rest) ----
// warp per output row; grid = 16384 blocks x 256 threads
__global__ void writeout_kernel(const float* __restrict__ hidden,
                                float* __restrict__ out) {
    int wg = blockIdx.x * (blockDim.x >> 5) + (threadIdx.x >> 5);
    int lane = threadIdx.x & 31;
    int b = wg >> 13;      // / 8192
    int i = wg & (SS - 1);
    float4* orow = (float4*)out + (size_t)wg * (DD / 4);
    if (i < g_count[b]) {
        int s = g_keptidx[b * SS + i];
        float inv = g_invnorm[b * SS + s];
        const float4* row = (const float4*)hidden + ((size_t)b * SS + s) * (DD / 4);
#pragma unroll
        for (int k = 0; k < 4; k++) {
            float4 x = row[lane + 32 * k];
            x.x *= inv; x.y *= inv; x.z *= inv; x.w *= inv;
            orow[lane + 32 * k] = x;
        }
    } else {
        float4 z = make_float4(0.f, 0.f, 0.f, 0.f);
#pragma unroll
        for (int k = 0; k < 4; k++) orow[lane + 32 * k] = z;
    }
}

// ---------------- kernel 6: binomial loss -> tail of output -------------------
__global__ void loss_kernel(float* __restrict__ out, long long out_size) {
    __shared__ double sh[BB];
    __shared__ float sh_loss;
    int tid = threadIdx.x;
    if (tid < BB) {
        double k = (double)g_count[tid];
        double n = (double)SS;
        double lp = lgamma(n + 1.0) - lgamma(k + 1.0) - lgamma(n - k + 1.0)
                  + k * log(0.2) + (n - k) * log1p(-0.2);
        sh[tid] = lp;
    }
    __syncthreads();
    if (tid == 0) {
        double m = 0.0;
        for (int b = 0; b < BB; b++) m += sh[b];
        m /= (double)BB;
        sh_loss = (float)(-m / (double)SS);
    }
    __syncthreads();
    long long start = (long long)BB * SS * DD;
    for (long long i = start + tid; i < out_size; i += blockDim.x) out[i] = sh_loss;
}

// ---------------- launch ------------------------------------------------------
extern "C" void kernel_launch(void* const* d_in, const int* in_sizes, int n_in,
                              void* d_out, int out_size) {
    const float* hidden = (const float*)d_in[0];
    const float* Wq     = (const float*)d_in[1];
    const float* Wk     = (const float*)d_in[2];
    const float* noise  = (const float*)d_in[3];
    float* out = (float*)d_out;

    zero_hs_kernel<<<(BB * DD + 511) / 512, 512>>>();
    norm_hs_kernel<<<512, 256>>>(hidden);
    matvec_kernel<<<BB, DD>>>(Wq, Wk);
    scores_kernel<<<512, 256>>>(hidden, noise);
    scan_kernel<<<BB, 1024>>>();
    writeout_kernel<<<(BB * SS) / 8, 256>>>(hidden, out);
    loss_kernel<<<1, 256>>>(out, (long long)out_size);
}

// round 2
// speedup vs baseline: 2.4472x; 2.4472x over previous
#include <cuda_runtime.h>
#include <math.h>

#define BB 16
#define SS 8192
#define DD 512
#define SCALE_F 0.125

// ---------------- scratch (__device__ globals; no allocations allowed) --------
__device__ double        g_hs[BB * DD];        // sum of normalized tokens per batch (fp64)
__device__ float         g_v[BB * DD];         // v[b] = Wq^T (Wk hs[b])
__device__ float         g_invnorm[BB * SS];   // 1/max(||hidden_row||, 1e-12)
__device__ unsigned char g_hard[BB * SS];      // boundary bits
__device__ int           g_keptidx[BB * SS];   // compacted kept indices per batch
__device__ int           g_count[BB];          // kept counts

// ---------------- kernel 0: zero hs ------------------------------------------
__global__ void zero_hs_kernel() {
    int i = blockIdx.x * blockDim.x + threadIdx.x;
    if (i < BB * DD) g_hs[i] = 0.0;
}

// ---------------- kernel 1: per-token norm + hs accumulation -----------------
// grid = 512 blocks (32 per batch), 256 threads (8 warps), warp = 32 tokens.
// 4 tokens in flight per iteration: 16 LDG.128 issued up-front (MLP=16),
// fp32 FFMA partials (4 independent chains/token), fp64 only for the
// interleaved cross-lane butterflies and the global accumulation.
__global__ void norm_hs_kernel(const float* __restrict__ hidden) {
    __shared__ double sh_acc[DD];
    int warp = threadIdx.x >> 5;
    int lane = threadIdx.x & 31;
    int batch = blockIdx.x >> 5;                    // 32 blocks per batch
    int tok0  = ((blockIdx.x & 31) * 8 + warp) * 32;

    for (int i = threadIdx.x; i < DD; i += blockDim.x) sh_acc[i] = 0.0;
    __syncthreads();

    float accf[16];
#pragma unroll
    for (int k = 0; k < 16; k++) accf[k] = 0.0f;

    const float4* base = (const float4*)(hidden + (size_t)batch * SS * DD);
    for (int t = 0; t < 32; t += 4) {
        // ---- batched loads: 4 tokens x 4 float4 each ----
        float4 x[4][4];
#pragma unroll
        for (int i = 0; i < 4; i++) {
            const float4* row = base + (size_t)(tok0 + t + i) * (DD / 4);
#pragma unroll
            for (int k = 0; k < 4; k++) x[i][k] = row[lane + 32 * k];
        }
        // ---- per-lane sum of squares: fp32, 4 independent chains/token ----
        double ss[4];
#pragma unroll
        for (int i = 0; i < 4; i++) {
            float s0 = 0.f, s1 = 0.f, s2 = 0.f, s3 = 0.f;
#pragma unroll
            for (int k = 0; k < 4; k++) {
                s0 = fmaf(x[i][k].x, x[i][k].x, s0);
                s1 = fmaf(x[i][k].y, x[i][k].y, s1);
                s2 = fmaf(x[i][k].z, x[i][k].z, s2);
                s3 = fmaf(x[i][k].w, x[i][k].w, s3);
            }
            ss[i] = ((double)s0 + (double)s1) + ((double)s2 + (double)s3);
        }
        // ---- interleaved fp64 butterflies (4 independent chains) ----
#pragma unroll
        for (int o = 16; o > 0; o >>= 1) {
#pragma unroll
            for (int i = 0; i < 4; i++)
                ss[i] += __shfl_xor_sync(0xffffffffu, ss[i], o);
        }
        float invf[4];
#pragma unroll
        for (int i = 0; i < 4; i++)
            invf[i] = 1.0f / fmaxf(sqrtf((float)ss[i]), 1e-12f);

        if (lane < 4) {
            // select (no dynamic register-array index -> no spill)
            float iv = invf[0];
            if (lane == 1) iv = invf[1];
            else if (lane == 2) iv = invf[2];
            else if (lane == 3) iv = invf[3];
            g_invnorm[batch * SS + tok0 + t + lane] = iv;
        }
        // ---- hs accumulation: 16 independent fp32 chains ----
#pragma unroll
        for (int i = 0; i < 4; i++) {
#pragma unroll
            for (int k = 0; k < 4; k++) {
                accf[4 * k + 0] = fmaf(x[i][k].x, invf[i], accf[4 * k + 0]);
                accf[4 * k + 1] = fmaf(x[i][k].y, invf[i], accf[4 * k + 1]);
                accf[4 * k + 2] = fmaf(x[i][k].z, invf[i], accf[4 * k + 2]);
                accf[4 * k + 3] = fmaf(x[i][k].w, invf[i], accf[4 * k + 3]);
            }
        }
    }
    // combine the 8 warps in shared fp64, then 512 global fp64 atomics/block
#pragma unroll
    for (int k = 0; k < 4; k++) {
        int c = 4 * (lane + 32 * k);
        atomicAdd(&sh_acc[c + 0], (double)accf[4 * k + 0]);
        atomicAdd(&sh_acc[c + 1], (double)accf[4 * k + 1]);
        atomicAdd(&sh_acc[c + 2], (double)accf[4 * k + 2]);
        atomicAdd(&sh_acc[c + 3], (double)accf[4 * k + 3]);
    }
    __syncthreads();
    for (int i = threadIdx.x; i < DD; i += blockDim.x)
        atomicAdd(&g_hs[batch * DD + i], sh_acc[i]);
}

// ---------------- kernel 2: v[b] = Wq^T (Wk hs[b])  (fp64, tiny) -------------
__global__ void matvec_kernel(const float* __restrict__ Wq, const float* __restrict__ Wk) {
    __shared__ double sh_hs[DD];
    __shared__ double sh_t[DD];
    int b = blockIdx.x;
    int tid = threadIdx.x;
    sh_hs[tid] = g_hs[b * DD + tid];
    __syncthreads();

    int warp = tid >> 5, lane = tid & 31;  // 16 warps
    for (int d = warp; d < DD; d += 16) {
        const float* wrow = Wk + (size_t)d * DD;
        double s = 0.0;
        for (int e = lane; e < DD; e += 32) s += (double)wrow[e] * sh_hs[e];
#pragma unroll
        for (int o = 16; o > 0; o >>= 1) s += __shfl_down_sync(0xffffffffu, s, o);
        if (lane == 0) sh_t[d] = s;
    }
    __syncthreads();

    double acc = 0.0;
    for (int d = 0; d < DD; d++) acc += (double)Wq[(size_t)d * DD + tid] * sh_t[d];
    g_v[b * DD + tid] = (float)acc;
}

// ---------------- kernel 3: scores + hard bits --------------------------------
// Same 4-token pipelined structure. v chunk lives in registers.
__global__ void scores_kernel(const float* __restrict__ hidden,
                              const float* __restrict__ noise) {
    __shared__ float sh_v[DD];
    int warp = threadIdx.x >> 5;
    int lane = threadIdx.x & 31;
    int batch = blockIdx.x >> 5;
    int tok0  = ((blockIdx.x & 31) * 8 + warp) * 32;

    for (int i = threadIdx.x; i < DD; i += blockDim.x) sh_v[i] = g_v[batch * DD + i];
    __syncthreads();

    const float4* vv = (const float4*)sh_v;
    float4 w[4];
#pragma unroll
    for (int k = 0; k < 4; k++) w[k] = vv[lane + 32 * k];

    const float4* base = (const float4*)(hidden + (size_t)batch * SS * DD);
    for (int t = 0; t < 32; t += 4) {
        float4 x[4][4];
#pragma unroll
        for (int i = 0; i < 4; i++) {
            const float4* row = base + (size_t)(tok0 + t + i) * (DD / 4);
#pragma unroll
            for (int k = 0; k < 4; k++) x[i][k] = row[lane + 32 * k];
        }
        double dot[4];
#pragma unroll
        for (int i = 0; i < 4; i++) {
            float s0 = 0.f, s1 = 0.f, s2 = 0.f, s3 = 0.f;
#pragma unroll
            for (int k = 0; k < 4; k++) {
                s0 = fmaf(x[i][k].x, w[k].x, s0);
                s1 = fmaf(x[i][k].y, w[k].y, s1);
                s2 = fmaf(x[i][k].z, w[k].z, s2);
                s3 = fmaf(x[i][k].w, w[k].w, s3);
            }
            dot[i] = ((double)s0 + (double)s1) + ((double)s2 + (double)s3);
        }
#pragma unroll
        for (int o = 16; o > 0; o >>= 1) {
#pragma unroll
            for (int i = 0; i < 4; i++)
                dot[i] += __shfl_xor_sync(0xffffffffu, dot[i], o);
        }
        if (lane < 4) {
            double d = dot[0];
            if (lane == 1) d = dot[1];
            else if (lane == 2) d = dot[2];
            else if (lane == 3) d = dot[3];
            int g = batch * SS + tok0 + t + lane;
            double score = SCALE_F * (double)g_invnorm[g] * d;
            float nz = noise[g];
            double logistic = (double)logf(nz) - (double)log1pf(-nz);
            g_hard[g] = (score + logistic > 0.0) ? 1 : 0;
        }
    }
}

// ---------------- kernel 4: per-batch stable compaction scan ------------------
__global__ void scan_kernel() {
    int b = blockIdx.x;
    int tid = threadIdx.x;
    const int TPT = SS / 1024;  // 8
    int base = b * SS + tid * TPT;

    int loc[TPT];
    int cnt = 0;
#pragma unroll
    for (int i = 0; i < TPT; i++) { loc[i] = g_hard[base + i]; cnt += loc[i]; }

    int lane = tid & 31, warp = tid >> 5;
    int v = cnt;
#pragma unroll
    for (int o = 1; o < 32; o <<= 1) {
        int n = __shfl_up_sync(0xffffffffu, v, o);
        if (lane >= o) v += n;
    }
    __shared__ int wsum[32];
    if (lane == 31) wsum[warp] = v;
    __syncthreads();
    if (warp == 0) {
        int w = wsum[lane];
#pragma unroll
        for (int o = 1; o < 32; o <<= 1) {
            int n = __shfl_up_sync(0xffffffffu, w, o);
            if (lane >= o) w += n;
        }
        wsum[lane] = w;
    }
    __syncthreads();
    int excl = (v - cnt) + (warp > 0 ? wsum[warp - 1] : 0);

    int pos = excl;
#pragma unroll
    for (int i = 0; i < TPT; i++)
        if (loc[i]) g_keptidx[b * SS + (pos++)] = tid * TPT + i;
    if (tid == 1023) g_count[b] = excl + cnt;
}

// ---------------- kernel 5: write pooled (gather kept rows, zero the rest) ----
__global__ void writeout_kernel(const float* __restrict__ hidden,
                                float* __restrict__ out) {
    int wg = blockIdx.x * (blockDim.x >> 5) + (threadIdx.x >> 5);
    int lane = threadIdx.x & 31;
    int b = wg >> 13;      // / 8192
    int i = wg & (SS - 1);
    float4* orow = (float4*)out + (size_t)wg * (DD / 4);
    if (i < g_count[b]) {
        int s = g_keptidx[b * SS + i];
        float inv = g_invnorm[b * SS + s];
        const float4* row = (const float4*)hidden + ((size_t)b * SS + s) * (DD / 4);
#pragma unroll
        for (int k = 0; k < 4; k++) {
            float4 x = row[lane + 32 * k];
            x.x *= inv; x.y *= inv; x.z *= inv; x.w *= inv;
            orow[lane + 32 * k] = x;
        }
    } else {
        float4 z = make_float4(0.f, 0.f, 0.f, 0.f);
#pragma unroll
        for (int k = 0; k < 4; k++) orow[lane + 32 * k] = z;
    }
}

// ---------------- kernel 6: binomial loss -> tail of output -------------------
__global__ void loss_kernel(float* __restrict__ out, long long out_size) {
    __shared__ double sh[BB];
    __shared__ float sh_loss;
    int tid = threadIdx.x;
    if (tid < BB) {
        double k = (double)g_count[tid];
        double n = (double)SS;
        double lp = lgamma(n + 1.0) - lgamma(k + 1.0) - lgamma(n - k + 1.0)
                  + k * log(0.2) + (n - k) * log1p(-0.2);
        sh[tid] = lp;
    }
    __syncthreads();
    if (tid == 0) {
        double m = 0.0;
        for (int b = 0; b < BB; b++) m += sh[b];
        m /= (double)BB;
        sh_loss = (float)(-m / (double)SS);
    }
    __syncthreads();
    long long start = (long long)BB * SS * DD;
    for (long long i = start + tid; i < out_size; i += blockDim.x) out[i] = sh_loss;
}

// ---------------- launch ------------------------------------------------------
extern "C" void kernel_launch(void* const* d_in, const int* in_sizes, int n_in,
                              void* d_out, int out_size) {
    const float* hidden = (const float*)d_in[0];
    const float* Wq     = (const float*)d_in[1];
    const float* Wk     = (const float*)d_in[2];
    const float* noise  = (const float*)d_in[3];
    float* out = (float*)d_out;

    zero_hs_kernel<<<(BB * DD + 511) / 512, 512>>>();
    norm_hs_kernel<<<512, 256>>>(hidden);
    matvec_kernel<<<BB, DD>>>(Wq, Wk);
    scores_kernel<<<512, 256>>>(hidden, noise);
    scan_kernel<<<BB, 1024>>>();
    writeout_kernel<<<(BB * SS) / 8, 256>>>(hidden, out);
    loss_kernel<<<1, 256>>>(out, (long long)out_size);
}

// round 3
// speedup vs baseline: 2.7852x; 1.1381x over previous
#include <cuda_runtime.h>
#include <math.h>

#define BB 16
#define SS 8192
#define DD 512
#define SCALE_F 0.125

// ---------------- scratch (__device__ globals; no allocations allowed) --------
__device__ double        g_hs[BB * DD];        // sum of normalized tokens per batch (fp64)
__device__ float         g_v[BB * DD];         // v[b] = Wq^T (Wk hs[b])
__device__ float         g_invnorm[BB * SS];   // 1/max(||hidden_row||, 1e-12)
__device__ unsigned char g_hard[BB * SS];      // boundary bits
__device__ int           g_keptidx[BB * SS];   // compacted kept indices per batch
__device__ int           g_count[BB];          // kept counts

// ---------------- kernel 0: zero hs ------------------------------------------
__global__ void zero_hs_kernel() {
    int i = blockIdx.x * blockDim.x + threadIdx.x;
    if (i < BB * DD) g_hs[i] = 0.0;
}

// ---------------- kernel 1: per-token norm + hs accumulation -----------------
// grid = 2048 blocks (128 per batch), 256 threads (8 warps), warp = 8 tokens.
// fp32 everywhere except the final cross-warp/cross-block hs combine (fp64).
__global__ void norm_hs_kernel(const float* __restrict__ hidden) {
    __shared__ float sh_warp[8 * DD];   // per-warp partial hs (16 KB)
    int warp = threadIdx.x >> 5;
    int lane = threadIdx.x & 31;
    int batch = blockIdx.x >> 7;                      // 128 blocks per batch
    int tok0  = ((blockIdx.x & 127) * 8 + warp) * 8;  // 8 tokens per warp

    float accf[16];
#pragma unroll
    for (int k = 0; k < 16; k++) accf[k] = 0.0f;

    const float4* base = (const float4*)(hidden + (size_t)batch * SS * DD);
#pragma unroll
    for (int t = 0; t < 8; t += 4) {
        // ---- batched loads: 4 tokens x 4 float4 each (16 LDG.128 in flight) ----
        float4 x[4][4];
#pragma unroll
        for (int i = 0; i < 4; i++) {
            const float4* row = base + (size_t)(tok0 + t + i) * (DD / 4);
#pragma unroll
            for (int k = 0; k < 4; k++) x[i][k] = row[lane + 32 * k];
        }
        // ---- per-lane sum of squares: fp32, 4 independent chains/token ----
        float ss[4];
#pragma unroll
        for (int i = 0; i < 4; i++) {
            float s0 = 0.f, s1 = 0.f, s2 = 0.f, s3 = 0.f;
#pragma unroll
            for (int k = 0; k < 4; k++) {
                s0 = fmaf(x[i][k].x, x[i][k].x, s0);
                s1 = fmaf(x[i][k].y, x[i][k].y, s1);
                s2 = fmaf(x[i][k].z, x[i][k].z, s2);
                s3 = fmaf(x[i][k].w, x[i][k].w, s3);
            }
            ss[i] = (s0 + s1) + (s2 + s3);
        }
        // ---- interleaved fp32 butterflies (4 independent chains) ----
#pragma unroll
        for (int o = 16; o > 0; o >>= 1) {
#pragma unroll
            for (int i = 0; i < 4; i++)
                ss[i] += __shfl_xor_sync(0xffffffffu, ss[i], o);
        }
        float invf[4];
#pragma unroll
        for (int i = 0; i < 4; i++)
            invf[i] = 1.0f / fmaxf(sqrtf(ss[i]), 1e-12f);

        if (lane < 4) {
            float iv = invf[0];
            if (lane == 1) iv = invf[1];
            else if (lane == 2) iv = invf[2];
            else if (lane == 3) iv = invf[3];
            g_invnorm[batch * SS + tok0 + t + lane] = iv;
        }
        // ---- hs accumulation: 16 independent fp32 chains ----
#pragma unroll
        for (int i = 0; i < 4; i++) {
#pragma unroll
            for (int k = 0; k < 4; k++) {
                accf[4 * k + 0] = fmaf(x[i][k].x, invf[i], accf[4 * k + 0]);
                accf[4 * k + 1] = fmaf(x[i][k].y, invf[i], accf[4 * k + 1]);
                accf[4 * k + 2] = fmaf(x[i][k].z, invf[i], accf[4 * k + 2]);
                accf[4 * k + 3] = fmaf(x[i][k].w, invf[i], accf[4 * k + 3]);
            }
        }
    }
    // ---- per-warp partials -> shared (no atomics) ----
    float* my = sh_warp + warp * DD;
#pragma unroll
    for (int k = 0; k < 4; k++) {
        int c = 4 * (lane + 32 * k);
        my[c + 0] = accf[4 * k + 0];
        my[c + 1] = accf[4 * k + 1];
        my[c + 2] = accf[4 * k + 2];
        my[c + 3] = accf[4 * k + 3];
    }
    __syncthreads();
    // ---- block combine in fp64, one global fp64 atomic per column ----
    for (int c = threadIdx.x; c < DD; c += blockDim.x) {
        double s = 0.0;
#pragma unroll
        for (int w = 0; w < 8; w++) s += (double)sh_warp[w * DD + c];
        atomicAdd(&g_hs[batch * DD + c], s);
    }
}

// ---------------- kernel 2: v[b] = Wq^T (Wk hs[b])  (fp64, tiny) -------------
__global__ void matvec_kernel(const float* __restrict__ Wq, const float* __restrict__ Wk) {
    __shared__ double sh_hs[DD];
    __shared__ double sh_t[DD];
    int b = blockIdx.x;
    int tid = threadIdx.x;
    sh_hs[tid] = g_hs[b * DD + tid];
    __syncthreads();

    int warp = tid >> 5, lane = tid & 31;  // 16 warps
    for (int d = warp; d < DD; d += 16) {
        const float* wrow = Wk + (size_t)d * DD;
        double s = 0.0;
        for (int e = lane; e < DD; e += 32) s += (double)wrow[e] * sh_hs[e];
#pragma unroll
        for (int o = 16; o > 0; o >>= 1) s += __shfl_down_sync(0xffffffffu, s, o);
        if (lane == 0) sh_t[d] = s;
    }
    __syncthreads();

    double acc = 0.0;
    for (int d = 0; d < DD; d++) acc += (double)Wq[(size_t)d * DD + tid] * sh_t[d];
    g_v[b * DD + tid] = (float)acc;
}

// ---------------- kernel 3: scores + hard bits --------------------------------
// grid = 2048 blocks, warp = 8 tokens. fp32 per-lane partials, fp64 butterfly
// (protects the threshold sign decisions).
__global__ void scores_kernel(const float* __restrict__ hidden,
                              const float* __restrict__ noise) {
    __shared__ float sh_v[DD];
    int warp = threadIdx.x >> 5;
    int lane = threadIdx.x & 31;
    int batch = blockIdx.x >> 7;
    int tok0  = ((blockIdx.x & 127) * 8 + warp) * 8;

    for (int i = threadIdx.x; i < DD; i += blockDim.x) sh_v[i] = g_v[batch * DD + i];
    __syncthreads();

    const float4* vv = (const float4*)sh_v;
    float4 w[4];
#pragma unroll
    for (int k = 0; k < 4; k++) w[k] = vv[lane + 32 * k];

    const float4* base = (const float4*)(hidden + (size_t)batch * SS * DD);
#pragma unroll
    for (int t = 0; t < 8; t += 4) {
        float4 x[4][4];
#pragma unroll
        for (int i = 0; i < 4; i++) {
            const float4* row = base + (size_t)(tok0 + t + i) * (DD / 4);
#pragma unroll
            for (int k = 0; k < 4; k++) x[i][k] = row[lane + 32 * k];
        }
        double dot[4];
#pragma unroll
        for (int i = 0; i < 4; i++) {
            float s0 = 0.f, s1 = 0.f, s2 = 0.f, s3 = 0.f;
#pragma unroll
            for (int k = 0; k < 4; k++) {
                s0 = fmaf(x[i][k].x, w[k].x, s0);
                s1 = fmaf(x[i][k].y, w[k].y, s1);
                s2 = fmaf(x[i][k].z, w[k].z, s2);
                s3 = fmaf(x[i][k].w, w[k].w, s3);
            }
            dot[i] = ((double)s0 + (double)s1) + ((double)s2 + (double)s3);
        }
#pragma unroll
        for (int o = 16; o > 0; o >>= 1) {
#pragma unroll
            for (int i = 0; i < 4; i++)
                dot[i] += __shfl_xor_sync(0xffffffffu, dot[i], o);
        }
        if (lane < 4) {
            double d = dot[0];
            if (lane == 1) d = dot[1];
            else if (lane == 2) d = dot[2];
            else if (lane == 3) d = dot[3];
            int g = batch * SS + tok0 + t + lane;
            double score = SCALE_F * (double)g_invnorm[g] * d;
            float nz = noise[g];
            double logistic = (double)logf(nz) - (double)log1pf(-nz);
            g_hard[g] = (score + logistic > 0.0) ? 1 : 0;
        }
    }
}

// ---------------- kernel 4: per-batch stable compaction scan ------------------
__global__ void scan_kernel() {
    int b = blockIdx.x;
    int tid = threadIdx.x;
    const int TPT = SS / 1024;  // 8
    int base = b * SS + tid * TPT;

    int loc[TPT];
    int cnt = 0;
#pragma unroll
    for (int i = 0; i < TPT; i++) { loc[i] = g_hard[base + i]; cnt += loc[i]; }

    int lane = tid & 31, warp = tid >> 5;
    int v = cnt;
#pragma unroll
    for (int o = 1; o < 32; o <<= 1) {
        int n = __shfl_up_sync(0xffffffffu, v, o);
        if (lane >= o) v += n;
    }
    __shared__ int wsum[32];
    if (lane == 31) wsum[warp] = v;
    __syncthreads();
    if (warp == 0) {
        int w = wsum[lane];
#pragma unroll
        for (int o = 1; o < 32; o <<= 1) {
            int n = __shfl_up_sync(0xffffffffu, w, o);
            if (lane >= o) w += n;
        }
        wsum[lane] = w;
    }
    __syncthreads();
    int excl = (v - cnt) + (warp > 0 ? wsum[warp - 1] : 0);

    int pos = excl;
#pragma unroll
    for (int i = 0; i < TPT; i++)
        if (loc[i]) g_keptidx[b * SS + (pos++)] = tid * TPT + i;
    if (tid == 1023) g_count[b] = excl + cnt;
}

// ---------------- kernel 5: write pooled (gather kept rows, zero the rest) ----
__global__ void writeout_kernel(const float* __restrict__ hidden,
                                float* __restrict__ out) {
    int wg = blockIdx.x * (blockDim.x >> 5) + (threadIdx.x >> 5);
    int lane = threadIdx.x & 31;
    int b = wg >> 13;      // / 8192
    int i = wg & (SS - 1);
    float4* orow = (float4*)out + (size_t)wg * (DD / 4);
    if (i < g_count[b]) {
        int s = g_keptidx[b * SS + i];
        float inv = g_invnorm[b * SS + s];
        const float4* row = (const float4*)hidden + ((size_t)b * SS + s) * (DD / 4);
#pragma unroll
        for (int k = 0; k < 4; k++) {
            float4 x = row[lane + 32 * k];
            x.x *= inv; x.y *= inv; x.z *= inv; x.w *= inv;
            orow[lane + 32 * k] = x;
        }
    } else {
        float4 z = make_float4(0.f, 0.f, 0.f, 0.f);
#pragma unroll
        for (int k = 0; k < 4; k++) orow[lane + 32 * k] = z;
    }
}

// ---------------- kernel 6: binomial loss -> tail of output -------------------
__global__ void loss_kernel(float* __restrict__ out, long long out_size) {
    __shared__ double sh[BB];
    __shared__ float sh_loss;
    int tid = threadIdx.x;
    if (tid < BB) {
        double k = (double)g_count[tid];
        double n = (double)SS;
        double lp = lgamma(n + 1.0) - lgamma(k + 1.0) - lgamma(n - k + 1.0)
                  + k * log(0.2) + (n - k) * log1p(-0.2);
        sh[tid] = lp;
    }
    __syncthreads();
    if (tid == 0) {
        double m = 0.0;
        for (int b = 0; b < BB; b++) m += sh[b];
        m /= (double)BB;
        sh_loss = (float)(-m / (double)SS);
    }
    __syncthreads();
    long long start = (long long)BB * SS * DD;
    for (long long i = start + tid; i < out_size; i += blockDim.x) out[i] = sh_loss;
}

// ---------------- launch ------------------------------------------------------
extern "C" void kernel_launch(void* const* d_in, const int* in_sizes, int n_in,
                              void* d_out, int out_size) {
    const float* hidden = (const float*)d_in[0];
    const float* Wq     = (const float*)d_in[1];
    const float* Wk     = (const float*)d_in[2];
    const float* noise  = (const float*)d_in[3];
    float* out = (float*)d_out;

    zero_hs_kernel<<<(BB * DD + 511) / 512, 512>>>();
    norm_hs_kernel<<<2048, 256>>>(hidden);
    matvec_kernel<<<BB, DD>>>(Wq, Wk);
    scores_kernel<<<2048, 256>>>(hidden, noise);
    scan_kernel<<<BB, 1024>>>();
    writeout_kernel<<<(BB * SS) / 8, 256>>>(hidden, out);
    loss_kernel<<<1, 256>>>(out, (long long)out_size);
}